// round 1
// baseline (speedup 1.0000x reference)
#include <cuda_runtime.h>
#include <math.h>

#define BB 2048
#define VV 3129
#define DD 768
#define LDG_ 3136            // padded leading dim for G
#define NPART 1024

// Scratch (static device globals — allowed; no runtime allocation)
__device__ float g_G[VV * LDG_];   // ~39.25 MB Gram matrix
__device__ float g_n[VV];          // row norms of G
__device__ int   g_map[VV];        // argmax mapping
__device__ float g_p1[NPART];      // softplus partials
__device__ float g_p2[NPART];      // gather-dot partials

// ---------------------------------------------------------------------------
// Kernel 1: G = E @ E^T   (fp32 SIMT tiled GEMM, 64x64 tile, 4x4 per thread)
// ---------------------------------------------------------------------------
__global__ void gram_kernel(const float* __restrict__ E) {
    __shared__ __align__(16) float As[16][68];
    __shared__ __align__(16) float Bs[16][68];

    const int t  = threadIdx.x;          // 0..255
    const int bm = blockIdx.y * 64;
    const int bn = blockIdx.x * 64;
    const int ty = t >> 4;               // 0..15 (m sub-tile)
    const int tx = t & 15;               // 0..15 (n sub-tile)

    float acc[4][4];
#pragma unroll
    for (int i = 0; i < 4; i++)
#pragma unroll
        for (int j = 0; j < 4; j++) acc[i][j] = 0.f;

    for (int k0 = 0; k0 < DD; k0 += 16) {
        // Load 64 rows x 16 k's for both tiles; coalesced along k.
#pragma unroll
        for (int i = 0; i < 4; i++) {
            int idx = t + i * 256;
            int m   = idx >> 4;
            int kk  = idx & 15;
            int ra  = bm + m;
            int rb  = bn + m;
            As[kk][m] = (ra < VV) ? E[ra * DD + k0 + kk] : 0.f;
            Bs[kk][m] = (rb < VV) ? E[rb * DD + k0 + kk] : 0.f;
        }
        __syncthreads();

#pragma unroll
        for (int kk = 0; kk < 16; kk++) {
            float4 a4 = *(const float4*)&As[kk][ty * 4];
            float4 b4 = *(const float4*)&Bs[kk][tx * 4];
            float av[4] = {a4.x, a4.y, a4.z, a4.w};
            float bv[4] = {b4.x, b4.y, b4.z, b4.w};
#pragma unroll
            for (int i = 0; i < 4; i++)
#pragma unroll
                for (int j = 0; j < 4; j++)
                    acc[i][j] = fmaf(av[i], bv[j], acc[i][j]);
        }
        __syncthreads();
    }

#pragma unroll
    for (int i = 0; i < 4; i++) {
        int row = bm + ty * 4 + i;
        if (row >= VV) continue;
#pragma unroll
        for (int j = 0; j < 4; j++) {
            int col = bn + tx * 4 + j;
            if (col < VV) g_G[row * LDG_ + col] = acc[i][j];
        }
    }
}

// ---------------------------------------------------------------------------
// Kernel 2: n[g] = sqrt(sum_j G[g,j]^2)
// ---------------------------------------------------------------------------
__global__ void norm_kernel() {
    int g = blockIdx.x;
    const float* __restrict__ row = &g_G[g * LDG_];
    float s = 0.f;
    for (int j = threadIdx.x; j < VV; j += 256) {
        float v = row[j];
        s = fmaf(v, v, s);
    }
    __shared__ float sh[256];
    sh[threadIdx.x] = s;
    __syncthreads();
    for (int st = 128; st > 0; st >>= 1) {
        if (threadIdx.x < st) sh[threadIdx.x] += sh[threadIdx.x + st];
        __syncthreads();
    }
    if (threadIdx.x == 0) g_n[g] = sqrtf(sh[0]);
}

// ---------------------------------------------------------------------------
// Kernel 3: map[g] = argmax_{j != g}  G[g,j] / (n_g*n_j + 1e-8)
// Division-free scan: den>0, so (a/den > best) <=> (a > best*den).
// First-occurrence tie semantics: strict > within thread; smaller index wins
// across threads.
// ---------------------------------------------------------------------------
__global__ void argmax_kernel() {
    int g = blockIdx.x;
    const float ng = g_n[g];
    const float* __restrict__ row = &g_G[g * LDG_];

    float best = -INFINITY;
    int   bj   = 0;
    for (int j = threadIdx.x; j < VV; j += 256) {
        if (j == g) continue;
        float den = fmaf(ng, g_n[j], 1e-8f);
        float a   = row[j];
        if (a > best * den) { best = a / den; bj = j; }
    }
    __shared__ float sv[256];
    __shared__ int   si[256];
    sv[threadIdx.x] = best;
    si[threadIdx.x] = bj;
    __syncthreads();
    for (int st = 128; st > 0; st >>= 1) {
        if (threadIdx.x < st) {
            float ov = sv[threadIdx.x + st];
            int   oi = si[threadIdx.x + st];
            if (ov > sv[threadIdx.x] ||
                (ov == sv[threadIdx.x] && oi < si[threadIdx.x])) {
                sv[threadIdx.x] = ov;
                si[threadIdx.x] = oi;
            }
        }
        __syncthreads();
    }
    if (threadIdx.x == 0) g_map[g] = si[0];
}

// ---------------------------------------------------------------------------
// Kernel 4: partial sums of softplus(pred) and pred[i,map[g]]*label[i,g]
// ---------------------------------------------------------------------------
__global__ void loss_kernel(const float* __restrict__ pred,
                            const float* __restrict__ label) {
    const int total = BB * VV;
    float s1 = 0.f, s2 = 0.f;
    for (int idx = blockIdx.x * blockDim.x + threadIdx.x; idx < total;
         idx += gridDim.x * blockDim.x) {
        float p = pred[idx];
        s1 += fmaxf(p, 0.f) + log1pf(expf(-fabsf(p)));
        float l = label[idx];
        if (l != 0.f) {
            int col     = idx % VV;
            int row_off = idx - col;          // row * VV
            int j       = g_map[col];
            s2 = fmaf(pred[row_off + j], l, s2);
        }
    }
    __shared__ float a[256], b[256];
    a[threadIdx.x] = s1;
    b[threadIdx.x] = s2;
    __syncthreads();
    for (int st = 128; st > 0; st >>= 1) {
        if (threadIdx.x < st) {
            a[threadIdx.x] += a[threadIdx.x + st];
            b[threadIdx.x] += b[threadIdx.x + st];
        }
        __syncthreads();
    }
    if (threadIdx.x == 0) {
        g_p1[blockIdx.x] = a[0];
        g_p2[blockIdx.x] = b[0];
    }
}

// ---------------------------------------------------------------------------
// Kernel 5: deterministic final reduction -> out[0] = (S1 - S2) / B
// ---------------------------------------------------------------------------
__global__ void final_kernel(float* __restrict__ out) {
    __shared__ float a[256], b[256];
    float s1 = 0.f, s2 = 0.f;
    for (int i = threadIdx.x; i < NPART; i += 256) {
        s1 += g_p1[i];
        s2 += g_p2[i];
    }
    a[threadIdx.x] = s1;
    b[threadIdx.x] = s2;
    __syncthreads();
    for (int st = 128; st > 0; st >>= 1) {
        if (threadIdx.x < st) {
            a[threadIdx.x] += a[threadIdx.x + st];
            b[threadIdx.x] += b[threadIdx.x + st];
        }
        __syncthreads();
    }
    if (threadIdx.x == 0) out[0] = (a[0] - b[0]) / (float)BB;
}

// ---------------------------------------------------------------------------
extern "C" void kernel_launch(void* const* d_in, const int* in_sizes, int n_in,
                              void* d_out, int out_size) {
    const float* pred  = (const float*)d_in[0];   // [B, V]
    const float* label = (const float*)d_in[1];   // [B, V]
    const float* E     = (const float*)d_in[2];   // [V, D]
    float* out = (float*)d_out;

    dim3 ggrid((VV + 63) / 64, (VV + 63) / 64);
    gram_kernel<<<ggrid, 256>>>(E);
    norm_kernel<<<VV, 256>>>();
    argmax_kernel<<<VV, 256>>>();
    loss_kernel<<<NPART, 256>>>(pred, label);
    final_kernel<<<1, 256>>>(out);
}

// round 2
// speedup vs baseline: 3.6092x; 3.6092x over previous
#include <cuda_runtime.h>
#include <cuda_bf16.h>
#include <math.h>

#define BB 2048
#define VV 3129
#define DD 768
#define VP 3200              // V padded to 25*128
#define NPART 1024

#define BM 128
#define BN 128
#define BK 32
#define SK 40                // BK + 8 pad (bank-conflict-free rows)

// Scratch (static device globals)
__device__ __nv_bfloat16 g_Eh[VP * DD];   // 4.9 MB, rows >= VV are zero
__device__ float g_G[VP * VP];            // 41 MB Gram matrix
__device__ float g_n[VV];                 // row norms
__device__ int   g_map[VV];               // argmax mapping
__device__ float g_p1[NPART];
__device__ float g_p2[NPART];

// ---------------------------------------------------------------------------
// Kernel 0: convert E fp32 -> bf16, zero-pad rows [VV, VP)
// ---------------------------------------------------------------------------
__global__ void convert_kernel(const float* __restrict__ E) {
    int idx = blockIdx.x * blockDim.x + threadIdx.x;   // over VP*DD
    if (idx >= VP * DD) return;
    int row = idx / DD;
    g_Eh[idx] = (row < VV) ? __float2bfloat16(E[idx]) : __float2bfloat16(0.f);
}

// ---------------------------------------------------------------------------
// Kernel 1: G = Eh @ Eh^T  via mma.sync m16n8k16 bf16 (fp32 accum)
// 256 threads, 128x128 block tile, 8 warps of 64x32, K-chunks of 32.
// ---------------------------------------------------------------------------
__device__ __forceinline__ void mma16816(float& c0, float& c1, float& c2, float& c3,
                                         unsigned a0, unsigned a1, unsigned a2, unsigned a3,
                                         unsigned b0, unsigned b1) {
    asm volatile(
        "mma.sync.aligned.m16n8k16.row.col.f32.bf16.bf16.f32 "
        "{%0,%1,%2,%3}, {%4,%5,%6,%7}, {%8,%9}, {%0,%1,%2,%3};\n"
        : "+f"(c0), "+f"(c1), "+f"(c2), "+f"(c3)
        : "r"(a0), "r"(a1), "r"(a2), "r"(a3), "r"(b0), "r"(b1));
}

__global__ __launch_bounds__(256, 2) void gram_kernel() {
    __shared__ __align__(16) __nv_bfloat16 As[BM * SK];
    __shared__ __align__(16) __nv_bfloat16 Bs[BN * SK];

    const int t    = threadIdx.x;
    const int warp = t >> 5;
    const int lane = t & 31;
    const int qrow = lane >> 2;        // 0..7
    const int qcol = lane & 3;         // 0..3

    const int m0 = (warp >> 2) * 64;   // warp m-offset in tile
    const int n0 = (warp & 3) * 32;    // warp n-offset in tile
    const int gm = blockIdx.y * BM;
    const int gn = blockIdx.x * BN;

    float acc[4][4][4];
#pragma unroll
    for (int i = 0; i < 4; i++)
#pragma unroll
        for (int j = 0; j < 4; j++)
#pragma unroll
            for (int c = 0; c < 4; c++) acc[i][j][c] = 0.f;

    for (int kc = 0; kc < DD; kc += BK) {
        // Load A tile (128x32) and B tile (128x32) as uint4 (8 bf16 each).
#pragma unroll
        for (int p = 0; p < 2; p++) {
            int idx = t + p * 256;         // 0..511
            int r   = idx >> 2;            // 0..127
            int grp = idx & 3;             // 0..3  (8 bf16 per group)
            const uint4 va = *(const uint4*)&g_Eh[(size_t)(gm + r) * DD + kc + grp * 8];
            const uint4 vb = *(const uint4*)&g_Eh[(size_t)(gn + r) * DD + kc + grp * 8];
            *(uint4*)&As[r * SK + grp * 8] = va;
            *(uint4*)&Bs[r * SK + grp * 8] = vb;
        }
        __syncthreads();

#pragma unroll
        for (int kk = 0; kk < BK; kk += 16) {
            unsigned af[4][4], bfr[4][2];
#pragma unroll
            for (int i = 0; i < 4; i++) {
                int r  = m0 + i * 16 + qrow;
                int cc = kk + qcol * 2;
                af[i][0] = *(const unsigned*)&As[r * SK + cc];
                af[i][1] = *(const unsigned*)&As[(r + 8) * SK + cc];
                af[i][2] = *(const unsigned*)&As[r * SK + cc + 8];
                af[i][3] = *(const unsigned*)&As[(r + 8) * SK + cc + 8];
            }
#pragma unroll
            for (int j = 0; j < 4; j++) {
                int rn = n0 + j * 8 + qrow;
                int cc = kk + qcol * 2;
                bfr[j][0] = *(const unsigned*)&Bs[rn * SK + cc];
                bfr[j][1] = *(const unsigned*)&Bs[rn * SK + cc + 8];
            }
#pragma unroll
            for (int i = 0; i < 4; i++)
#pragma unroll
                for (int j = 0; j < 4; j++)
                    mma16816(acc[i][j][0], acc[i][j][1], acc[i][j][2], acc[i][j][3],
                             af[i][0], af[i][1], af[i][2], af[i][3],
                             bfr[j][0], bfr[j][1]);
        }
        __syncthreads();
    }

    // Epilogue: write C (all indices in-bounds thanks to VP padding)
#pragma unroll
    for (int i = 0; i < 4; i++) {
        int row = gm + m0 + i * 16 + qrow;
#pragma unroll
        for (int j = 0; j < 4; j++) {
            int col = gn + n0 + j * 8 + qcol * 2;
            *(float2*)&g_G[(size_t)row * VP + col]       = make_float2(acc[i][j][0], acc[i][j][1]);
            *(float2*)&g_G[(size_t)(row + 8) * VP + col] = make_float2(acc[i][j][2], acc[i][j][3]);
        }
    }
}

// ---------------------------------------------------------------------------
// Kernel 2: n[g] = sqrt(sum_j G[g,j]^2)
// ---------------------------------------------------------------------------
__global__ void norm_kernel() {
    int g = blockIdx.x;
    const float* __restrict__ row = &g_G[(size_t)g * VP];
    float s = 0.f;
    for (int j = threadIdx.x; j < VV; j += 256) {
        float v = row[j];
        s = fmaf(v, v, s);
    }
    __shared__ float sh[256];
    sh[threadIdx.x] = s;
    __syncthreads();
    for (int st = 128; st > 0; st >>= 1) {
        if (threadIdx.x < st) sh[threadIdx.x] += sh[threadIdx.x + st];
        __syncthreads();
    }
    if (threadIdx.x == 0) g_n[g] = sqrtf(sh[0]);
}

// ---------------------------------------------------------------------------
// Kernel 3: map[g] = argmax_{j != g}  G[g,j] / (n_g*n_j + 1e-8)
// ---------------------------------------------------------------------------
__global__ void argmax_kernel() {
    int g = blockIdx.x;
    const float ng = g_n[g];
    const float* __restrict__ row = &g_G[(size_t)g * VP];

    float best = -INFINITY;
    int   bj   = 0;
    for (int j = threadIdx.x; j < VV; j += 256) {
        if (j == g) continue;
        float den = fmaf(ng, g_n[j], 1e-8f);
        float a   = row[j];
        if (a > best * den) { best = a / den; bj = j; }
    }
    __shared__ float sv[256];
    __shared__ int   si[256];
    sv[threadIdx.x] = best;
    si[threadIdx.x] = bj;
    __syncthreads();
    for (int st = 128; st > 0; st >>= 1) {
        if (threadIdx.x < st) {
            float ov = sv[threadIdx.x + st];
            int   oi = si[threadIdx.x + st];
            if (ov > sv[threadIdx.x] ||
                (ov == sv[threadIdx.x] && oi < si[threadIdx.x])) {
                sv[threadIdx.x] = ov;
                si[threadIdx.x] = oi;
            }
        }
        __syncthreads();
    }
    if (threadIdx.x == 0) g_map[g] = si[0];
}

// ---------------------------------------------------------------------------
// Kernel 4: partials of softplus(pred) and pred[i,map[g]]*label[i,g]
// ---------------------------------------------------------------------------
__device__ __forceinline__ float softplus_fast(float p) {
    return fmaxf(p, 0.f) + log1pf(__expf(-fabsf(p)));
}

__global__ void loss_kernel(const float* __restrict__ pred,
                            const float* __restrict__ label) {
    const int total4 = (BB * VV) / 4;     // divisible: 2048*3129 % 4 == 0
    const float4* __restrict__ pred4  = (const float4*)pred;
    const float4* __restrict__ label4 = (const float4*)label;

    float s1 = 0.f, s2 = 0.f;
    for (int i = blockIdx.x * blockDim.x + threadIdx.x; i < total4;
         i += gridDim.x * blockDim.x) {
        float4 p = pred4[i];
        float4 l = label4[i];
        s1 += softplus_fast(p.x) + softplus_fast(p.y) +
              softplus_fast(p.z) + softplus_fast(p.w);
        if (l.x != 0.f || l.y != 0.f || l.z != 0.f || l.w != 0.f) {
            int base = i * 4;
#pragma unroll
            for (int c = 0; c < 4; c++) {
                float lv = (c == 0) ? l.x : (c == 1) ? l.y : (c == 2) ? l.z : l.w;
                if (lv != 0.f) {
                    int idx     = base + c;
                    int col     = idx % VV;
                    int row_off = idx - col;
                    s2 = fmaf(pred[row_off + g_map[col]], lv, s2);
                }
            }
        }
    }
    __shared__ float a[256], b[256];
    a[threadIdx.x] = s1;
    b[threadIdx.x] = s2;
    __syncthreads();
    for (int st = 128; st > 0; st >>= 1) {
        if (threadIdx.x < st) {
            a[threadIdx.x] += a[threadIdx.x + st];
            b[threadIdx.x] += b[threadIdx.x + st];
        }
        __syncthreads();
    }
    if (threadIdx.x == 0) {
        g_p1[blockIdx.x] = a[0];
        g_p2[blockIdx.x] = b[0];
    }
}

// ---------------------------------------------------------------------------
// Kernel 5: deterministic final reduction
// ---------------------------------------------------------------------------
__global__ void final_kernel(float* __restrict__ out) {
    __shared__ float a[256], b[256];
    float s1 = 0.f, s2 = 0.f;
    for (int i = threadIdx.x; i < NPART; i += 256) {
        s1 += g_p1[i];
        s2 += g_p2[i];
    }
    a[threadIdx.x] = s1;
    b[threadIdx.x] = s2;
    __syncthreads();
    for (int st = 128; st > 0; st >>= 1) {
        if (threadIdx.x < st) {
            a[threadIdx.x] += a[threadIdx.x + st];
            b[threadIdx.x] += b[threadIdx.x + st];
        }
        __syncthreads();
    }
    if (threadIdx.x == 0) out[0] = (a[0] - b[0]) / (float)BB;
}

// ---------------------------------------------------------------------------
extern "C" void kernel_launch(void* const* d_in, const int* in_sizes, int n_in,
                              void* d_out, int out_size) {
    const float* pred  = (const float*)d_in[0];   // [B, V]
    const float* label = (const float*)d_in[1];   // [B, V]
    const float* E     = (const float*)d_in[2];   // [V, D]
    float* out = (float*)d_out;

    convert_kernel<<<(VP * DD + 255) / 256, 256>>>(E);
    dim3 ggrid(VP / BN, VP / BM);                 // 25 x 25
    gram_kernel<<<ggrid, 256>>>();
    norm_kernel<<<VV, 256>>>();
    argmax_kernel<<<VV, 256>>>();
    loss_kernel<<<NPART, 256>>>(pred, label);
    final_kernel<<<1, 256>>>(out);
}